// round 13
// baseline (speedup 1.0000x reference)
#include <cuda_runtime.h>
#include <cuda_bf16.h>
#include <math.h>
#include <stdint.h>

#define T_STEPS 200
#define B 256
#define XD 128
#define H 512
#define ZD 64
#define OD 256
#define G3 1536
#define NBLK 148
#define NTHR 512

#define AST 72
#define A_L 9216
#define W_H 18432
#define W_L 27648
#define BUF_H 36864
#define SM_TILES 1024
#define SMEM_BYTES (SM_TILES + 2 * BUF_H * 2)

#define OFF_PXW1 0
#define OFF_PXW2 65536
#define OFF_PZW  327680
#define OFF_EW1  360448
#define OFF_EW2  884736
#define OFF_EMW  1146880
#define OFF_ESW  1179648
#define OFF_PRW  1212416
#define OFF_PMW  1474560
#define OFF_PSW  1507328
#define OFF_DW1  1540096
#define OFF_DW2  2064384
#define OFF_DLW  2326528
#define OFF_GWIH 2457600
#define OFF_GWHH 4030464
#define W_TOTAL  4816896

#define BH (B * H)
#define BZ (B * ZD)
#define BO (B * OD)
#define BG (B * G3)

// ---------------- scratch ----------------
__device__ float g_phi[(size_t)T_STEPS * BH];
__device__ float g_e1pre[(size_t)T_STEPS * BH];
__device__ float g_gxpre[(size_t)T_STEPS * BG];
__device__ float g_h [BH];
__device__ float g_pz[BH];
__device__ float g_gh[BG];
__device__ float g_e1hP[8][BH];
__device__ float g_prP [4][BH];
__device__ float g_e2P [8][BH];
__device__ float g_d1P [2][4][BH];
__device__ float g_d2P [2][4][BH];
__device__ float g_emP [8][BZ];
__device__ float g_esP [8][BZ];
__device__ float g_pmP [8][BZ];
__device__ float g_psP [8][BZ];
__device__ float g_gxP [4][BG];
__device__ __align__(16) __nv_bfloat16 g_whi[W_TOTAL];
__device__ __align__(16) __nv_bfloat16 g_wlo[W_TOTAL];

// ---------------- dataflow counters (monotonic, line-padded) ----------------
#define CI_H    0
#define CI_E1H  1
#define CI_PR   2
#define CI_D1A  3
#define CI_E2   4
#define CI_EMES 5
#define CI_PMPS 6
#define CI_WR   7
#define CI_PZ   8
#define CI_GX   9
#define CI_D1B  10
#define CI_D2   11
#define CI_GH   12
#define CI_LOG  13
__device__ volatile unsigned g_cnt[16 * 32];

__device__ __forceinline__ void arrive(int i) {
    __syncthreads();
    if (threadIdx.x == 0) {
        __threadfence();
        atomicAdd((unsigned*)&g_cnt[i << 5], 1u);
    }
}
__device__ __forceinline__ void waitc(int i, unsigned v) {
    if (threadIdx.x == 0) {
        while (g_cnt[i << 5] < v) { }
        __threadfence();
    }
    __syncthreads();
}

// ---------------- grid barrier (preamble/tail only) ----------------
__device__ unsigned int g_bar = 0;
__device__ volatile unsigned int g_sense = 0;

__device__ __forceinline__ void gsyncN(unsigned* gen, unsigned nexp, bool last) {
    __syncthreads();
    if (threadIdx.x == 0) {
        __threadfence();
        unsigned g = *gen;
        if (atomicAdd(&g_bar, 1u) == nexp - 1u) {
            g_bar = 0u;
            __threadfence();
            g_sense = last ? 0u : (g + 1u);
        } else {
            while (g_sense == g) { }
            __threadfence();
        }
    }
    __syncthreads();
    (*gen)++;
}

// ---------------- helpers ----------------
__device__ __forceinline__ uint32_t smem_u32(const void* p) {
    uint32_t a;
    asm("{ .reg .u64 t; cvta.to.shared.u64 t, %1; cvt.u32.u64 %0, t; }" : "=r"(a) : "l"(p));
    return a;
}
__device__ __forceinline__ void ldsm4(uint32_t* r, uint32_t addr) {
    asm volatile("ldmatrix.sync.aligned.m8n8.x4.shared.b16 {%0,%1,%2,%3}, [%4];"
                 : "=r"(r[0]), "=r"(r[1]), "=r"(r[2]), "=r"(r[3]) : "r"(addr));
}
__device__ __forceinline__ void mma16816(float* d, const uint32_t* a, const uint32_t* b) {
    asm volatile(
        "mma.sync.aligned.m16n8k16.row.col.f32.bf16.bf16.f32 "
        "{%0,%1,%2,%3}, {%4,%5,%6,%7}, {%8,%9}, {%0,%1,%2,%3};"
        : "+f"(d[0]), "+f"(d[1]), "+f"(d[2]), "+f"(d[3])
        : "r"(a[0]), "r"(a[1]), "r"(a[2]), "r"(a[3]), "r"(b[0]), "r"(b[1]));
}
__device__ __forceinline__ float actf(float v, int act) {
    if (act == 1) return fmaxf(v, 0.f);
    return v;
}
__device__ __forceinline__ float spf(float v) {
    return fmaxf(v, 0.f) + log1pf(expf(-fabsf(v)));
}
__device__ __forceinline__ uint32_t bpack(float a, float b) {
    __nv_bfloat162 h = __floats2bfloat162_rn(a, b);
    return *(uint32_t*)&h;
}

// A-source: mode 0 plain p0; mode 1 relu((p0?) + Σ_{s<n} pa[s*ps]); mode 2 p0*sp(Σpa)+Σpb
struct ASrc {
    const float *p0, *pa, *pb;
    int n, ps, mode;
};
__device__ __forceinline__ void ld8(const float* p, size_t o, float* v) {
    float4 a = *(const float4*)(p + o);
    float4 b = *(const float4*)(p + o + 4);
    v[0] = a.x; v[1] = a.y; v[2] = a.z; v[3] = a.w;
    v[4] = b.x; v[5] = b.y; v[6] = b.z; v[7] = b.w;
}
__device__ __forceinline__ void fetch8(float* v, const ASrc& a, size_t o) {
    if (a.mode == 0) { ld8(a.p0, o, v); return; }
    if (a.mode == 1) {
        if (a.p0) ld8(a.p0, o, v);
        else {
#pragma unroll
            for (int i = 0; i < 8; i++) v[i] = 0.f;
        }
        for (int s = 0; s < a.n; s++) {
            float w[8];
            ld8(a.pa + (size_t)s * a.ps, o, w);
#pragma unroll
            for (int i = 0; i < 8; i++) v[i] += w[i];
        }
#pragma unroll
        for (int i = 0; i < 8; i++) v[i] = fmaxf(v[i], 0.f);
        return;
    }
    float w[8], u[8];
#pragma unroll
    for (int i = 0; i < 8; i++) { w[i] = 0.f; u[i] = 0.f; }
    ld8(a.p0, o, v);
    for (int s = 0; s < a.n; s++) {
        float x[8];
        ld8(a.pa + (size_t)s * a.ps, o, x);
#pragma unroll
        for (int i = 0; i < 8; i++) w[i] += x[i];
        ld8(a.pb + (size_t)s * a.ps, o, x);
#pragma unroll
        for (int i = 0; i < 8; i++) u[i] += x[i];
    }
#pragma unroll
    for (int i = 0; i < 8; i++) v[i] = v[i] * spf(w[i]) + u[i];
}

// prefetch next task's W chunk-0 tile into buffer 0 (hi+lo)
__device__ __forceinline__ void stageW0(char* smc, int nrows, int col0,
                                        int woff, int ldw, int wkbase) {
    uint16_t* bb = (uint16_t*)(smc + SM_TILES);
    for (int it = threadIdx.x; it < nrows * 8; it += NTHR) {
        int r = it >> 3, kg = (it & 7) << 3;
        size_t o = (size_t)woff + (size_t)(col0 + r) * ldw + wkbase + kg;
        *(uint4*)(bb + W_H + r * AST + kg) = *(const uint4*)(g_whi + o);
        *(uint4*)(bb + W_L + r * AST + kg) = *(const uint4*)(g_wlo + o);
    }
}

// ---------------- mma.sync 128 x (WN*64) GEMM tile, 16 warps ----------------
template<int WN>
__device__ __noinline__ void gemmT(
    char* smc, int row0, int col0,
    ASrc a, int k0, int akbase, int klen,
    int woff, int ldw, int wkbase,
    const float* __restrict__ bias, const float* __restrict__ eadd,
    float* __restrict__ C, int ldc, int act, int preW)
{
    const int tid = threadIdx.x;
    const int lane = tid & 31, wid = tid >> 5;
    const int wm = wid & 3, wn = wid >> 2;
    const int NC = klen >> 6;
    const uint32_t smb = smem_u32(smc) + SM_TILES;

    float acc[2][2 * WN][4];
#pragma unroll
    for (int i = 0; i < 2; i++)
#pragma unroll
        for (int j = 0; j < 2 * WN; j++)
#pragma unroll
            for (int q = 0; q < 4; q++) acc[i][j][q] = 0.f;

    auto stage = [&](int b, int kb, int doW) {
        uint16_t* bb = (uint16_t*)(smc + SM_TILES) + b * BUF_H;
#pragma unroll 2
        for (int it = tid; it < 1024; it += NTHR) {
            int r = it >> 3, kg = (it & 7) << 3;
            size_t o = (size_t)(row0 + r) * k0 + akbase + kb + kg;
            float v[8];
            fetch8(v, a, o);
            uint32_t hw[4], lw[4];
#pragma unroll
            for (int j = 0; j < 4; j++) {
                float h0 = __bfloat162float(__float2bfloat16(v[2 * j]));
                float h1 = __bfloat162float(__float2bfloat16(v[2 * j + 1]));
                hw[j] = bpack(v[2 * j], v[2 * j + 1]);
                lw[j] = bpack(v[2 * j] - h0, v[2 * j + 1] - h1);
            }
            *(uint4*)(bb + r * AST + kg) = make_uint4(hw[0], hw[1], hw[2], hw[3]);
            *(uint4*)(bb + A_L + r * AST + kg) = make_uint4(lw[0], lw[1], lw[2], lw[3]);
        }
        if (doW) {
#pragma unroll 2
            for (int it = tid; it < WN * 512; it += NTHR) {
                int r = it >> 3, kg = (it & 7) << 3;
                size_t o = (size_t)woff + (size_t)(col0 + r) * ldw + wkbase + kb + kg;
                *(uint4*)(bb + W_H + r * AST + kg) = *(const uint4*)(g_whi + o);
                *(uint4*)(bb + W_L + r * AST + kg) = *(const uint4*)(g_wlo + o);
            }
        }
    };

    const int arow = wm * 32 + (lane & 15);
    const int acolh = (lane >> 4) << 3;
    const int brow = ((lane >> 4) << 3) + (lane & 7);
    const int bko = ((lane >> 3) & 1) << 3;

    stage(0, 0, !preW);
    __syncthreads();

    for (int c = 0; c < NC; c++) {
        if (c + 1 < NC) stage((c + 1) & 1, (c + 1) << 6, 1);
        uint32_t bufb = smb + (uint32_t)(c & 1) * (BUF_H * 2);
#pragma unroll
        for (int ks = 0; ks < 4; ks++) {
            uint32_t ah[2][4], al[2][4];
#pragma unroll
            for (int mt = 0; mt < 2; mt++) {
                uint32_t ad = bufb + (uint32_t)(((arow + mt * 16) * AST + (ks << 4) + acolh) << 1);
                ldsm4(ah[mt], ad);
                ldsm4(al[mt], ad + (A_L << 1));
            }
#pragma unroll
            for (int ntp = 0; ntp < WN; ntp++) {
                uint32_t bd = bufb + (uint32_t)((W_H + (wn * (WN * 16) + ntp * 16 + brow) * AST
                                                 + (ks << 4) + bko) << 1);
                uint32_t bh[4], bl[4];
                ldsm4(bh, bd);
                ldsm4(bl, bd + ((W_L - W_H) << 1));
#pragma unroll
                for (int mt = 0; mt < 2; mt++) {
                    mma16816(acc[mt][2 * ntp],     ah[mt], bh);
                    mma16816(acc[mt][2 * ntp],     ah[mt], bl);
                    mma16816(acc[mt][2 * ntp],     al[mt], bh);
                    mma16816(acc[mt][2 * ntp + 1], ah[mt], bh + 2);
                    mma16816(acc[mt][2 * ntp + 1], ah[mt], bl + 2);
                    mma16816(acc[mt][2 * ntp + 1], al[mt], bh + 2);
                }
            }
        }
        __syncthreads();
    }

#pragma unroll
    for (int mt = 0; mt < 2; mt++) {
        int r1 = row0 + wm * 32 + mt * 16 + (lane >> 2);
#pragma unroll
        for (int nt = 0; nt < 2 * WN; nt++) {
            int cc = col0 + wn * (WN * 16) + nt * 8 + ((lane & 3) << 1);
            float bx = 0.f, by = 0.f;
            if (bias) { float2 bv = *(const float2*)(bias + cc); bx = bv.x; by = bv.y; }
            float o0 = acc[mt][nt][0] + bx, o1 = acc[mt][nt][1] + by;
            float o2 = acc[mt][nt][2] + bx, o3 = acc[mt][nt][3] + by;
            if (eadd) {
                float2 a0 = *(const float2*)(eadd + (size_t)r1 * ldc + cc);
                float2 a1 = *(const float2*)(eadd + (size_t)(r1 + 8) * ldc + cc);
                o0 += a0.x; o1 += a0.y; o2 += a1.x; o3 += a1.y;
            }
            *(float2*)(C + (size_t)r1 * ldc + cc) =
                make_float2(actf(o0, act), actf(o1, act));
            *(float2*)(C + (size_t)(r1 + 8) * ldc + cc) =
                make_float2(actf(o2, act), actf(o3, act));
        }
    }
}

// ---------------- params ----------------
struct Params {
    const float *x, *eps;
    const float *pxw1, *pxb1, *pxw2, *pxb2;
    const float *pzw, *pzb;
    const float *ew1, *eb1, *ew2, *eb2, *emw, *emb, *esw, *esb;
    const float *prw, *prb, *pmw, *pmb, *psw, *psb;
    const float *dw1, *db1, *dw2, *db2, *dlw, *dlb;
    const float *gwih, *gbih, *gwhh, *gbhh;
    float *oz, *olog, *oem, *oes, *opm, *ops, *okld;
};

__global__ void __launch_bounds__(NTHR, 1) vrnn_kernel(Params p) {
    extern __shared__ char smc[];
    unsigned gen = 0;
    const int tid = threadIdx.x;
    const int blk = blockIdx.x;

    for (int e = blk * NTHR + tid; e < BH; e += NBLK * NTHR) g_h[e] = 0.f;

#define PLAIN(ptr) ASrc{ptr, 0, 0, 0, 0, 0}

    // ---- weight transpose + bf16 hi/lo split ----
    {
        const float* wsrc[15] = {p.pxw1, p.pxw2, p.pzw, p.ew1, p.ew2, p.emw, p.esw, p.prw,
                                 p.pmw, p.psw, p.dw1, p.dw2, p.dlw, p.gwih, p.gwhh};
        const int wk[15] = {128, 512, 64, 1024, 512, 512, 512, 512, 512, 512, 1024, 512, 512, 1024, 512};
        const int wn[15] = {512, 512, 512, 512, 512, 64, 64, 512, 64, 64, 512, 512, 256, 1536, 1536};
        const int wof[15] = {OFF_PXW1, OFF_PXW2, OFF_PZW, OFF_EW1, OFF_EW2, OFF_EMW, OFF_ESW, OFF_PRW,
                             OFF_PMW, OFF_PSW, OFF_DW1, OFF_DW2, OFF_DLW, OFF_GWIH, OFF_GWHH};
        float* tile = (float*)(smc + SM_TILES);
        for (int task = blk; task < 1176; task += NBLK) {
            int tt = task, w = 0;
            for (; w < 15; w++) {
                int nt = (wk[w] >> 6) * (wn[w] >> 6);
                if (tt < nt) break;
                tt -= nt;
            }
            int tkc = wk[w] >> 6;
            int k0 = (tt % tkc) * 64, n0 = (tt / tkc) * 64;
            const float* src = wsrc[w];
            int K = wk[w], N = wn[w];
            for (int it = tid; it < 4096; it += NTHR) {
                int i = it >> 6, j = it & 63;
                tile[i * 68 + j] = src[(size_t)(k0 + i) * N + n0 + j];
            }
            __syncthreads();
            for (int it = tid; it < 4096; it += NTHR) {
                int j = it >> 6, i = it & 63;
                float v = tile[i * 68 + j];
                __nv_bfloat16 hi = __float2bfloat16(v);
                size_t o = (size_t)wof[w] + (size_t)(n0 + j) * K + k0 + i;
                g_whi[o] = hi;
                g_wlo[o] = __float2bfloat16(v - __bfloat162float(hi));
            }
            __syncthreads();
        }
    }
    gsyncN(&gen, NBLK, false);

    // ---- preamble ----
    for (int idx = blk; idx < 1600; idx += NBLK) {
        int tm = idx >> 2, tn = idx & 3;
        gemmT<2>(smc, tm * 128, tn * 128, PLAIN(p.x), XD, 0, 128,
                 OFF_PXW1, XD, 0, p.pxb1, 0, g_e1pre, H, 1, 0);
    }
    gsyncN(&gen, NBLK, false);
    for (int idx = blk; idx < 1600; idx += NBLK) {
        int tm = idx >> 2, tn = idx & 3;
        gemmT<2>(smc, tm * 128, tn * 128, PLAIN(g_e1pre), H, 0, 512,
                 OFF_PXW2, H, 0, p.pxb2, 0, g_phi, H, 1, 0);
    }
    gsyncN(&gen, NBLK, false);
    for (int idx = blk; idx < 6400; idx += NBLK) {
        if (idx < 1600) {
            int tm = idx >> 2, tn = idx & 3;
            gemmT<2>(smc, tm * 128, tn * 128, PLAIN(g_phi), H, 0, 512,
                     OFF_EW1, 1024, 0, p.eb1, 0, g_e1pre, H, 0, 0);
        } else {
            int i = idx - 1600;
            int tm = i / 12, tn = i % 12;
            gemmT<2>(smc, tm * 128, tn * 128, PLAIN(g_phi), H, 0, 512,
                     OFF_GWIH, 1024, 0, p.gbih, 0, g_gxpre, G3, 0, 0);
        }
    }
    gsyncN(&gen, NBLK, false);

    // ================= dataflow main loop =================
    for (int t = 0; t < T_STEPS; t++) {
        const float* e1pre_t = g_e1pre + (size_t)t * BH;
        float (*d1)[BH] = g_d1P[t & 1];
        const unsigned T1 = (unsigned)(t + 1);

        if (blk < 64) {
            // e1h (gate h) -> e2 (gate e1h) -> gx task blk (gate pz)
            int tile = blk >> 3, s = blk & 7;
            int tm = tile >> 2, tn = tile & 3;
            stageW0(smc, 128, tn * 128, OFF_EW1, 1024, 512 + s * 64);
            waitc(CI_H, 16u * (unsigned)t);
            gemmT<2>(smc, tm * 128, tn * 128, PLAIN(g_h), H, s * 64, 64,
                     OFF_EW1, 1024, 512 + s * 64, 0, 0, g_e1hP[s], H, 0, 1);
            arrive(CI_E1H);

            stageW0(smc, 128, tn * 128, OFF_EW2, H, s * 64);
            waitc(CI_E1H, 64u * T1);
            {
                ASrc a = {e1pre_t, g_e1hP[0], 0, 8, BH, 1};
                gemmT<2>(smc, tm * 128, tn * 128, a, H, s * 64, 64,
                         OFF_EW2, H, s * 64, s == 0 ? p.eb2 : 0, 0, g_e2P[s], H, 0, 1);
            }
            arrive(CI_E2);

            int q = blk; int gt = q >> 2, gs = q & 3;
            stageW0(smc, 128, (gt % 12) * 128, OFF_GWIH, 1024, 512 + gs * 128);
            waitc(CI_PZ, 8u * T1);
            gemmT<2>(smc, (gt / 12) * 128, (gt % 12) * 128, PLAIN(g_pz), H, gs * 128, 128,
                     OFF_GWIH, 1024, 512 + gs * 128, 0, 0, g_gxP[gs], G3, 0, 1);
            arrive(CI_GX);
        } else if (blk < 96) {
            // pr -> pmps -> d1b -> d2
            int i = blk - 64; int tile = i >> 2, s = i & 3;
            int tm = tile >> 2, tn = tile & 3;
            stageW0(smc, 128, tn * 128, OFF_PRW, H, s * 128);
            waitc(CI_H, 16u * (unsigned)t);
            gemmT<2>(smc, tm * 128, tn * 128, PLAIN(g_h), H, s * 128, 128,
                     OFF_PRW, H, s * 128, s == 0 ? p.prb : 0, 0, g_prP[s], H, 0, 1);
            arrive(CI_PR);

            int isps = i >> 4, j = i & 15, t2 = j >> 3, s2 = j & 7;
            stageW0(smc, 64, 0, isps ? OFF_PSW : OFF_PMW, H, s2 * 64);
            waitc(CI_PR, 32u * T1);
            {
                ASrc a = {0, g_prP[0], 0, 4, BH, 1};
                gemmT<1>(smc, t2 * 128, 0, a, H, s2 * 64, 64,
                         isps ? OFF_PSW : OFF_PMW, H, s2 * 64,
                         s2 == 0 ? (isps ? p.psb : p.pmb) : 0, 0,
                         isps ? g_psP[s2] : g_pmP[s2], ZD, 0, 1);
            }
            arrive(CI_PMPS);

            stageW0(smc, 128, tn * 128, OFF_DW1, 1024, s * 128);
            waitc(CI_PZ, 8u * T1);
            waitc(CI_D1A, 32u * T1);
            gemmT<2>(smc, tm * 128, tn * 128, PLAIN(g_pz), H, s * 128, 128,
                     OFF_DW1, 1024, s * 128, 0, d1[s], d1[s], H, 0, 1);
            arrive(CI_D1B);

            stageW0(smc, 128, tn * 128, OFF_DW2, H, s * 128);
            waitc(CI_D1B, 32u * T1);
            waitc(CI_LOG, 4u * (unsigned)t);
            {
                ASrc a = {0, d1[0], 0, 4, BH, 1};
                gemmT<2>(smc, tm * 128, tn * 128, a, H, s * 128, 128,
                         OFF_DW2, H, s * 128, s == 0 ? p.db2 : 0, 0,
                         g_d2P[t & 1][s], H, 0, 1);
            }
            arrive(CI_D2);
        } else if (blk < 128) {
            // d1a -> emes -> {gx | pz | writers} -> (GRU for blk>=112)
            int i = blk - 96; int tile = i >> 2, s = i & 3;
            int tm = tile >> 2, tn = tile & 3;
            stageW0(smc, 128, tn * 128, OFF_DW1, 1024, 512 + s * 128);
            waitc(CI_H, 16u * (unsigned)t);
            gemmT<2>(smc, tm * 128, tn * 128, PLAIN(g_h), H, s * 128, 128,
                     OFF_DW1, 1024, 512 + s * 128, s == 0 ? p.db1 : 0, 0, d1[s], H, 0, 1);
            arrive(CI_D1A);

            int ises = i >> 4, j = i & 15, t2 = j >> 3, s2 = j & 7;
            stageW0(smc, 64, 0, ises ? OFF_ESW : OFF_EMW, H, s2 * 64);
            waitc(CI_E2, 64u * T1);
            {
                ASrc a = {0, g_e2P[0], 0, 8, BH, 1};
                gemmT<1>(smc, t2 * 128, 0, a, H, s2 * 64, 64,
                         ises ? OFF_ESW : OFF_EMW, H, s2 * 64,
                         s2 == 0 ? (ises ? p.esb : p.emb) : 0, 0,
                         ises ? g_esP[s2] : g_emP[s2], ZD, 0, 1);
            }
            arrive(CI_EMES);

            const float* eps_t = p.eps + (size_t)t * BZ;
            if (blk < 112) {
                int q = 64 + (blk - 96); int gt = q >> 2, gs = q & 3;
                stageW0(smc, 128, (gt % 12) * 128, OFF_GWIH, 1024, 512 + gs * 128);
                waitc(CI_PZ, 8u * T1);
                gemmT<2>(smc, (gt / 12) * 128, (gt % 12) * 128, PLAIN(g_pz), H, gs * 128, 128,
                         OFF_GWIH, 1024, 512 + gs * 128, 0, 0, g_gxP[gs], G3, 0, 1);
                arrive(CI_GX);
            } else if (blk < 120) {
                int q = blk - 112;
                stageW0(smc, 128, (q & 3) * 128, OFF_PZW, ZD, 0);
                waitc(CI_EMES, 32u * T1);
                {
                    ASrc a = {eps_t, g_esP[0], g_emP[0], 8, BZ, 2};
                    gemmT<2>(smc, (q >> 2) * 128, (q & 3) * 128, a, ZD, 0, 64,
                             OFF_PZW, ZD, 0, p.pzb, 0, g_pz, H, 1, 1);
                }
                arrive(CI_PZ);
            } else {
                waitc(CI_EMES, 32u * T1);
                waitc(CI_PMPS, 32u * T1);
                {
                    float* z_t  = p.oz  + (size_t)t * BZ;
                    float* em_t = p.oem + (size_t)t * BZ;
                    float* es_t = p.oes + (size_t)t * BZ;
                    float* pm_t = p.opm + (size_t)t * BZ;
                    float* ps_t = p.ops + (size_t)t * BZ;
                    float* kl_t = p.okld + (size_t)t * BZ;
                    int base = (blk - 120) * 2048;
                    for (int e = base + tid; e < base + 2048; e += NTHR) {
                        float em = 0.f, es = 0.f, pm = 0.f, ps = 0.f;
#pragma unroll
                        for (int s3 = 0; s3 < 8; s3++) {
                            em += g_emP[s3][e]; es += g_esP[s3][e];
                            pm += g_pmP[s3][e]; ps += g_psP[s3][e];
                        }
                        es = spf(es); ps = spf(ps);
                        em_t[e] = em; es_t[e] = es; pm_t[e] = pm; ps_t[e] = ps;
                        z_t[e] = eps_t[e] * es + em;
                        float d = em - pm;
                        kl_t[e] = 0.5f * (2.f * logf(ps) - 2.f * logf(es)
                                          + (es * es + d * d) / (ps * ps) - 1.f);
                    }
                }
                arrive(CI_WR);
            }
            if (blk >= 112) {
                // GRU (16 blocks)
                waitc(CI_GX, 96u * T1);
                waitc(CI_GH, 16u * T1);
                waitc(CI_WR, 8u * T1);
                waitc(CI_D1B, 32u * T1);
                waitc(CI_D2, 32u * (unsigned)t);
                const float* gp = g_gxpre + (size_t)t * BG;
                int base = (blk - 112) * 8192;
                for (int e = base + tid; e < base + 8192; e += NTHR) {
                    int b = e >> 9, j2 = e & 511;
                    size_t o = (size_t)b * G3 + j2;
                    float xr = gp[o], xz = gp[o + 512], xn = gp[o + 1024];
#pragma unroll
                    for (int s3 = 0; s3 < 4; s3++) {
                        xr += g_gxP[s3][o]; xz += g_gxP[s3][o + 512]; xn += g_gxP[s3][o + 1024];
                    }
                    float hr = g_gh[o], hz = g_gh[o + 512], hn = g_gh[o + 1024];
                    float rg = 1.f / (1.f + expf(-(xr + hr)));
                    float ug = 1.f / (1.f + expf(-(xz + hz)));
                    float ng = tanhf(xn + rg * hn);
                    g_h[e] = (1.f - ug) * ng + ug * g_h[e];
                }
                arrive(CI_H);
            }
        } else if (blk < 144) {
            // gh (1-2 tiles, unsplit) -> gx task 80+(blk-128)
            int b = blk - 128;
            {
                int tile = b; int tm = tile / 12, tn = tile % 12;
                stageW0(smc, 128, tn * 128, OFF_GWHH, H, 0);
                waitc(CI_H, 16u * (unsigned)t);
                gemmT<2>(smc, tm * 128, tn * 128, PLAIN(g_h), H, 0, 512,
                         OFF_GWHH, H, 0, p.gbhh, 0, g_gh, G3, 0, 1);
                if (b < 8) {
                    int tile2 = 16 + b; int tm2 = tile2 / 12, tn2 = tile2 % 12;
                    gemmT<2>(smc, tm2 * 128, tn2 * 128, PLAIN(g_h), H, 0, 512,
                             OFF_GWHH, H, 0, p.gbhh, 0, g_gh, G3, 0, 0);
                }
                arrive(CI_GH);
            }
            int q = 80 + b; int gt = q >> 2, gs = q & 3;
            stageW0(smc, 128, (gt % 12) * 128, OFF_GWIH, 1024, 512 + gs * 128);
            waitc(CI_PZ, 8u * T1);
            gemmT<2>(smc, (gt / 12) * 128, (gt % 12) * 128, PLAIN(g_pz), H, gs * 128, 128,
                     OFF_GWIH, 1024, 512 + gs * 128, 0, 0, g_gxP[gs], G3, 0, 1);
            arrive(CI_GX);
        } else {
            // logits(t-1) unsplit (4 blocks)
            int b = blk - 144;
            waitc(CI_D2, 32u * (unsigned)t);
            if (t > 0) {
                ASrc a = {0, g_d2P[(t + 1) & 1][0], 0, 4, BH, 1};
                gemmT<2>(smc, (b >> 1) * 128, (b & 1) * 128, a, H, 0, 512,
                         OFF_DLW, H, 0, p.dlb, 0,
                         p.olog + (size_t)(t - 1) * BO, OD, 0, 0);
            }
            arrive(CI_LOG);
        }
    }

    // ---- tail: logits(199) ----
    gsyncN(&gen, NBLK, false);
    if (blk < 4) {
        ASrc a = {0, g_d2P[(T_STEPS - 1) & 1][0], 0, 4, BH, 1};
        gemmT<2>(smc, (blk >> 1) * 128, (blk & 1) * 128, a, H, 0, 512,
                 OFF_DLW, H, 0, p.dlb, 0,
                 p.olog + (size_t)(T_STEPS - 1) * BO, OD, 0, 0);
    }
    gsyncN(&gen, NBLK, false);
    if (blk == 0) {
        for (int i = tid; i < 16 * 32; i += NTHR) g_cnt[i] = 0u;
    }
    gsyncN(&gen, NBLK, true);
}

extern "C" void kernel_launch(void* const* d_in, const int* in_sizes, int n_in,
                              void* d_out, int out_size) {
    Params p;
    p.x    = (const float*)d_in[0];
    p.eps  = (const float*)d_in[1];
    p.pxw1 = (const float*)d_in[2];  p.pxb1 = (const float*)d_in[3];
    p.pxw2 = (const float*)d_in[4];  p.pxb2 = (const float*)d_in[5];
    p.pzw  = (const float*)d_in[6];  p.pzb  = (const float*)d_in[7];
    p.ew1  = (const float*)d_in[8];  p.eb1  = (const float*)d_in[9];
    p.ew2  = (const float*)d_in[10]; p.eb2  = (const float*)d_in[11];
    p.emw  = (const float*)d_in[12]; p.emb  = (const float*)d_in[13];
    p.esw  = (const float*)d_in[14]; p.esb  = (const float*)d_in[15];
    p.prw  = (const float*)d_in[16]; p.prb  = (const float*)d_in[17];
    p.pmw  = (const float*)d_in[18]; p.pmb  = (const float*)d_in[19];
    p.psw  = (const float*)d_in[20]; p.psb  = (const float*)d_in[21];
    p.dw1  = (const float*)d_in[22]; p.db1  = (const float*)d_in[23];
    p.dw2  = (const float*)d_in[24]; p.db2  = (const float*)d_in[25];
    p.dlw  = (const float*)d_in[26]; p.dlb  = (const float*)d_in[27];
    if (in_sizes[29] == 3 * H) {
        p.gwih = (const float*)d_in[28]; p.gbih = (const float*)d_in[29];
        p.gwhh = (const float*)d_in[30]; p.gbhh = (const float*)d_in[31];
    } else {
        p.gwih = (const float*)d_in[28]; p.gwhh = (const float*)d_in[29];
        p.gbih = (const float*)d_in[30]; p.gbhh = (const float*)d_in[31];
    }

    float* o = (float*)d_out;
    size_t TBZ = (size_t)T_STEPS * B * ZD;
    size_t TBO = (size_t)T_STEPS * B * OD;
    p.oz   = o;
    p.olog = o + TBZ;
    p.oem  = p.olog + TBO;
    p.oes  = p.oem + TBZ;
    p.opm  = p.oes + TBZ;
    p.ops  = p.opm + TBZ;
    p.okld = p.ops + TBZ;

    static bool attr_set = false;
    if (!attr_set) {
        cudaFuncSetAttribute(vrnn_kernel, cudaFuncAttributeMaxDynamicSharedMemorySize, SMEM_BYTES);
        attr_set = true;
    }
    vrnn_kernel<<<NBLK, NTHR, SMEM_BYTES>>>(p);
}

// round 14
// speedup vs baseline: 1.2909x; 1.2909x over previous
#include <cuda_runtime.h>
#include <cuda_bf16.h>
#include <math.h>
#include <stdint.h>

#define T_STEPS 200
#define B 256
#define XD 128
#define H 512
#define ZD 64
#define OD 256
#define G3 1536
#define NBLK 148
#define NTHR 512

#define AST 72
#define A_L 9216
#define W_H 18432
#define W_L 27648
#define BUF_H 36864
#define SM_TILES 1024
#define SMEM_BYTES (SM_TILES + 2 * BUF_H * 2)

#define OFF_PXW1 0
#define OFF_PXW2 65536
#define OFF_PZW  327680
#define OFF_EW1  360448
#define OFF_EW2  884736
#define OFF_EMW  1146880
#define OFF_ESW  1179648
#define OFF_PRW  1212416
#define OFF_PMW  1474560
#define OFF_PSW  1507328
#define OFF_DW1  1540096
#define OFF_DW2  2064384
#define OFF_DLW  2326528
#define OFF_GWIH 2457600
#define OFF_GWHH 4030464
#define W_TOTAL  4816896

#define BH (B * H)
#define BZ (B * ZD)
#define BO (B * OD)
#define BG (B * G3)

// ---------------- scratch ----------------
__device__ float g_phi[(size_t)T_STEPS * BH];
__device__ float g_e1pre[(size_t)T_STEPS * BH];
__device__ float g_gxpre[(size_t)T_STEPS * BG];
__device__ float g_h [BH];
__device__ float g_pz[BH];
__device__ float g_gh[BG];
__device__ float g_e1hP[8][BH];
__device__ float g_prP [8][BH];
__device__ float g_e2P [8][BH];
__device__ float g_d1P [2][4][BH];
__device__ float g_d2P [2][4][BH];
__device__ float g_emP [8][BZ];
__device__ float g_esP [8][BZ];
__device__ float g_pmP [8][BZ];
__device__ float g_psP [8][BZ];
__device__ float g_gxP [4][BG];
__device__ __align__(16) __nv_bfloat16 g_whi[W_TOTAL];
__device__ __align__(16) __nv_bfloat16 g_wlo[W_TOTAL];

// ---------------- grid barrier (split arrive/wait, busy spin) ----------------
__device__ unsigned int g_bar = 0;
__device__ volatile unsigned int g_sense = 0;

__device__ __forceinline__ void garr(unsigned gen, unsigned nexp, bool last) {
    __syncthreads();
    if (threadIdx.x == 0) {
        __threadfence();
        if (atomicAdd(&g_bar, 1u) == nexp - 1u) {
            g_bar = 0u;
            __threadfence();
            g_sense = last ? 0u : (gen + 1u);
        }
    }
}
__device__ __forceinline__ void gwt(unsigned* gen) {
    if (threadIdx.x == 0) {
        unsigned g = *gen;
        while (g_sense == g) { }
        __threadfence();
    }
    __syncthreads();
    (*gen)++;
}
__device__ __forceinline__ void gsyncN(unsigned* gen, unsigned nexp, bool last) {
    garr(*gen, nexp, last);
    gwt(gen);
}

// ---------------- helpers ----------------
__device__ __forceinline__ uint32_t smem_u32(const void* p) {
    uint32_t a;
    asm("{ .reg .u64 t; cvta.to.shared.u64 t, %1; cvt.u32.u64 %0, t; }" : "=r"(a) : "l"(p));
    return a;
}
__device__ __forceinline__ void ldsm4(uint32_t* r, uint32_t addr) {
    asm volatile("ldmatrix.sync.aligned.m8n8.x4.shared.b16 {%0,%1,%2,%3}, [%4];"
                 : "=r"(r[0]), "=r"(r[1]), "=r"(r[2]), "=r"(r[3]) : "r"(addr));
}
__device__ __forceinline__ void mma16816(float* d, const uint32_t* a, const uint32_t* b) {
    asm volatile(
        "mma.sync.aligned.m16n8k16.row.col.f32.bf16.bf16.f32 "
        "{%0,%1,%2,%3}, {%4,%5,%6,%7}, {%8,%9}, {%0,%1,%2,%3};"
        : "+f"(d[0]), "+f"(d[1]), "+f"(d[2]), "+f"(d[3])
        : "r"(a[0]), "r"(a[1]), "r"(a[2]), "r"(a[3]), "r"(b[0]), "r"(b[1]));
}
__device__ __forceinline__ float actf(float v, int act) {
    if (act == 1) return fmaxf(v, 0.f);
    return v;
}
__device__ __forceinline__ float spf(float v) {
    return fmaxf(v, 0.f) + log1pf(expf(-fabsf(v)));
}
__device__ __forceinline__ uint32_t bpack(float a, float b) {
    __nv_bfloat162 h = __floats2bfloat162_rn(a, b);
    return *(uint32_t*)&h;
}

// A-source: mode 0 plain p0; mode 1 relu((p0?) + Σ_{s<n} pa[s*ps]); mode 2 p0*sp(Σpa)+Σpb
struct ASrc {
    const float *p0, *pa, *pb;
    int n, ps, mode;
};
__device__ __forceinline__ void ld8(const float* p, size_t o, float* v) {
    float4 a = *(const float4*)(p + o);
    float4 b = *(const float4*)(p + o + 4);
    v[0] = a.x; v[1] = a.y; v[2] = a.z; v[3] = a.w;
    v[4] = b.x; v[5] = b.y; v[6] = b.z; v[7] = b.w;
}
__device__ __forceinline__ void fetch8(float* v, const ASrc& a, size_t o) {
    if (a.mode == 0) { ld8(a.p0, o, v); return; }
    if (a.mode == 1) {
        if (a.p0) ld8(a.p0, o, v);
        else {
#pragma unroll
            for (int i = 0; i < 8; i++) v[i] = 0.f;
        }
        for (int s = 0; s < a.n; s++) {
            float w[8];
            ld8(a.pa + (size_t)s * a.ps, o, w);
#pragma unroll
            for (int i = 0; i < 8; i++) v[i] += w[i];
        }
#pragma unroll
        for (int i = 0; i < 8; i++) v[i] = fmaxf(v[i], 0.f);
        return;
    }
    float w[8], u[8];
#pragma unroll
    for (int i = 0; i < 8; i++) { w[i] = 0.f; u[i] = 0.f; }
    ld8(a.p0, o, v);
    for (int s = 0; s < a.n; s++) {
        float x[8];
        ld8(a.pa + (size_t)s * a.ps, o, x);
#pragma unroll
        for (int i = 0; i < 8; i++) w[i] += x[i];
        ld8(a.pb + (size_t)s * a.ps, o, x);
#pragma unroll
        for (int i = 0; i < 8; i++) u[i] += x[i];
    }
#pragma unroll
    for (int i = 0; i < 8; i++) v[i] = v[i] * spf(w[i]) + u[i];
}

// prefetch next task's W chunk-0 tile into buffer 0 (hi+lo)
__device__ __forceinline__ void stageW0(char* smc, int nrows, int col0,
                                        int woff, int ldw, int wkbase) {
    uint16_t* bb = (uint16_t*)(smc + SM_TILES);
    for (int it = threadIdx.x; it < nrows * 8; it += NTHR) {
        int r = it >> 3, kg = (it & 7) << 3;
        size_t o = (size_t)woff + (size_t)(col0 + r) * ldw + wkbase + kg;
        *(uint4*)(bb + W_H + r * AST + kg) = *(const uint4*)(g_whi + o);
        *(uint4*)(bb + W_L + r * AST + kg) = *(const uint4*)(g_wlo + o);
    }
}

// ---------------- mma.sync 128 x (WN*64) GEMM tile, 16 warps ----------------
template<int WN>
__device__ __noinline__ void gemmT(
    char* smc, int row0, int col0,
    ASrc a, int k0, int akbase, int klen,
    int woff, int ldw, int wkbase,
    const float* __restrict__ bias, const float* __restrict__ eadd,
    float* __restrict__ C, int ldc, int act, int preW)
{
    const int tid = threadIdx.x;
    const int lane = tid & 31, wid = tid >> 5;
    const int wm = wid & 3, wn = wid >> 2;
    const int NC = klen >> 6;
    const uint32_t smb = smem_u32(smc) + SM_TILES;

    float acc[2][2 * WN][4];
#pragma unroll
    for (int i = 0; i < 2; i++)
#pragma unroll
        for (int j = 0; j < 2 * WN; j++)
#pragma unroll
            for (int q = 0; q < 4; q++) acc[i][j][q] = 0.f;

    auto stage = [&](int b, int kb, int doW) {
        uint16_t* bb = (uint16_t*)(smc + SM_TILES) + b * BUF_H;
#pragma unroll 2
        for (int it = tid; it < 1024; it += NTHR) {
            int r = it >> 3, kg = (it & 7) << 3;
            size_t o = (size_t)(row0 + r) * k0 + akbase + kb + kg;
            float v[8];
            fetch8(v, a, o);
            uint32_t hw[4], lw[4];
#pragma unroll
            for (int j = 0; j < 4; j++) {
                float h0 = __bfloat162float(__float2bfloat16(v[2 * j]));
                float h1 = __bfloat162float(__float2bfloat16(v[2 * j + 1]));
                hw[j] = bpack(v[2 * j], v[2 * j + 1]);
                lw[j] = bpack(v[2 * j] - h0, v[2 * j + 1] - h1);
            }
            *(uint4*)(bb + r * AST + kg) = make_uint4(hw[0], hw[1], hw[2], hw[3]);
            *(uint4*)(bb + A_L + r * AST + kg) = make_uint4(lw[0], lw[1], lw[2], lw[3]);
        }
        if (doW) {
#pragma unroll 2
            for (int it = tid; it < WN * 512; it += NTHR) {
                int r = it >> 3, kg = (it & 7) << 3;
                size_t o = (size_t)woff + (size_t)(col0 + r) * ldw + wkbase + kb + kg;
                *(uint4*)(bb + W_H + r * AST + kg) = *(const uint4*)(g_whi + o);
                *(uint4*)(bb + W_L + r * AST + kg) = *(const uint4*)(g_wlo + o);
            }
        }
    };

    const int arow = wm * 32 + (lane & 15);
    const int acolh = (lane >> 4) << 3;
    const int brow = ((lane >> 4) << 3) + (lane & 7);
    const int bko = ((lane >> 3) & 1) << 3;

    stage(0, 0, !preW);
    __syncthreads();

    for (int c = 0; c < NC; c++) {
        if (c + 1 < NC) stage((c + 1) & 1, (c + 1) << 6, 1);
        uint32_t bufb = smb + (uint32_t)(c & 1) * (BUF_H * 2);
#pragma unroll
        for (int ks = 0; ks < 4; ks++) {
            uint32_t ah[2][4], al[2][4];
#pragma unroll
            for (int mt = 0; mt < 2; mt++) {
                uint32_t ad = bufb + (uint32_t)(((arow + mt * 16) * AST + (ks << 4) + acolh) << 1);
                ldsm4(ah[mt], ad);
                ldsm4(al[mt], ad + (A_L << 1));
            }
#pragma unroll
            for (int ntp = 0; ntp < WN; ntp++) {
                uint32_t bd = bufb + (uint32_t)((W_H + (wn * (WN * 16) + ntp * 16 + brow) * AST
                                                 + (ks << 4) + bko) << 1);
                uint32_t bh[4], bl[4];
                ldsm4(bh, bd);
                ldsm4(bl, bd + ((W_L - W_H) << 1));
#pragma unroll
                for (int mt = 0; mt < 2; mt++) {
                    mma16816(acc[mt][2 * ntp],     ah[mt], bh);
                    mma16816(acc[mt][2 * ntp],     ah[mt], bl);
                    mma16816(acc[mt][2 * ntp],     al[mt], bh);
                    mma16816(acc[mt][2 * ntp + 1], ah[mt], bh + 2);
                    mma16816(acc[mt][2 * ntp + 1], ah[mt], bl + 2);
                    mma16816(acc[mt][2 * ntp + 1], al[mt], bh + 2);
                }
            }
        }
        __syncthreads();
    }

#pragma unroll
    for (int mt = 0; mt < 2; mt++) {
        int r1 = row0 + wm * 32 + mt * 16 + (lane >> 2);
#pragma unroll
        for (int nt = 0; nt < 2 * WN; nt++) {
            int cc = col0 + wn * (WN * 16) + nt * 8 + ((lane & 3) << 1);
            float bx = 0.f, by = 0.f;
            if (bias) { float2 bv = *(const float2*)(bias + cc); bx = bv.x; by = bv.y; }
            float o0 = acc[mt][nt][0] + bx, o1 = acc[mt][nt][1] + by;
            float o2 = acc[mt][nt][2] + bx, o3 = acc[mt][nt][3] + by;
            if (eadd) {
                float2 a0 = *(const float2*)(eadd + (size_t)r1 * ldc + cc);
                float2 a1 = *(const float2*)(eadd + (size_t)(r1 + 8) * ldc + cc);
                o0 += a0.x; o1 += a0.y; o2 += a1.x; o3 += a1.y;
            }
            *(float2*)(C + (size_t)r1 * ldc + cc) =
                make_float2(actf(o0, act), actf(o1, act));
            *(float2*)(C + (size_t)(r1 + 8) * ldc + cc) =
                make_float2(actf(o2, act), actf(o3, act));
        }
    }
}

// ---------------- params ----------------
struct Params {
    const float *x, *eps;
    const float *pxw1, *pxb1, *pxw2, *pxb2;
    const float *pzw, *pzb;
    const float *ew1, *eb1, *ew2, *eb2, *emw, *emb, *esw, *esb;
    const float *prw, *prb, *pmw, *pmb, *psw, *psb;
    const float *dw1, *db1, *dw2, *db2, *dlw, *dlb;
    const float *gwih, *gbih, *gwhh, *gbhh;
    float *oz, *olog, *oem, *oes, *opm, *ops, *okld;
};

__global__ void __launch_bounds__(NTHR, 1) vrnn_kernel(Params p) {
    extern __shared__ char smc[];
    unsigned gen = 0;
    const int tid = threadIdx.x;
    const int blk = blockIdx.x;

    for (int e = blk * NTHR + tid; e < BH; e += NBLK * NTHR) g_h[e] = 0.f;

#define PLAIN(ptr) ASrc{ptr, 0, 0, 0, 0, 0}

    // ---- weight transpose + bf16 hi/lo split ----
    {
        const float* wsrc[15] = {p.pxw1, p.pxw2, p.pzw, p.ew1, p.ew2, p.emw, p.esw, p.prw,
                                 p.pmw, p.psw, p.dw1, p.dw2, p.dlw, p.gwih, p.gwhh};
        const int wk[15] = {128, 512, 64, 1024, 512, 512, 512, 512, 512, 512, 1024, 512, 512, 1024, 512};
        const int wn[15] = {512, 512, 512, 512, 512, 64, 64, 512, 64, 64, 512, 512, 256, 1536, 1536};
        const int wof[15] = {OFF_PXW1, OFF_PXW2, OFF_PZW, OFF_EW1, OFF_EW2, OFF_EMW, OFF_ESW, OFF_PRW,
                             OFF_PMW, OFF_PSW, OFF_DW1, OFF_DW2, OFF_DLW, OFF_GWIH, OFF_GWHH};
        float* tile = (float*)(smc + SM_TILES);
        for (int task = blk; task < 1176; task += NBLK) {
            int tt = task, w = 0;
            for (; w < 15; w++) {
                int nt = (wk[w] >> 6) * (wn[w] >> 6);
                if (tt < nt) break;
                tt -= nt;
            }
            int tkc = wk[w] >> 6;
            int k0 = (tt % tkc) * 64, n0 = (tt / tkc) * 64;
            const float* src = wsrc[w];
            int K = wk[w], N = wn[w];
            for (int it = tid; it < 4096; it += NTHR) {
                int i = it >> 6, j = it & 63;
                tile[i * 68 + j] = src[(size_t)(k0 + i) * N + n0 + j];
            }
            __syncthreads();
            for (int it = tid; it < 4096; it += NTHR) {
                int j = it >> 6, i = it & 63;
                float v = tile[i * 68 + j];
                __nv_bfloat16 hi = __float2bfloat16(v);
                size_t o = (size_t)wof[w] + (size_t)(n0 + j) * K + k0 + i;
                g_whi[o] = hi;
                g_wlo[o] = __float2bfloat16(v - __bfloat162float(hi));
            }
            __syncthreads();
        }
    }
    gsyncN(&gen, NBLK, false);

    // ---- preamble ----
    for (int idx = blk; idx < 1600; idx += NBLK) {
        int tm = idx >> 2, tn = idx & 3;
        gemmT<2>(smc, tm * 128, tn * 128, PLAIN(p.x), XD, 0, 128,
                 OFF_PXW1, XD, 0, p.pxb1, 0, g_e1pre, H, 1, 0);
    }
    gsyncN(&gen, NBLK, false);
    for (int idx = blk; idx < 1600; idx += NBLK) {
        int tm = idx >> 2, tn = idx & 3;
        gemmT<2>(smc, tm * 128, tn * 128, PLAIN(g_e1pre), H, 0, 512,
                 OFF_PXW2, H, 0, p.pxb2, 0, g_phi, H, 1, 0);
    }
    gsyncN(&gen, NBLK, false);
    for (int idx = blk; idx < 6400; idx += NBLK) {
        if (idx < 1600) {
            int tm = idx >> 2, tn = idx & 3;
            gemmT<2>(smc, tm * 128, tn * 128, PLAIN(g_phi), H, 0, 512,
                     OFF_EW1, 1024, 0, p.eb1, 0, g_e1pre, H, 0, 0);
        } else {
            int i = idx - 1600;
            int tm = i / 12, tn = i % 12;
            gemmT<2>(smc, tm * 128, tn * 128, PLAIN(g_phi), H, 0, 512,
                     OFF_GWIH, 1024, 0, p.gbih, 0, g_gxpre, G3, 0, 0);
        }
    }
    // enter loop; chain blocks prefetch P1's W under this barrier
    garr(gen, NBLK, false);
    if (blk < 64) {
        int tile = blk >> 3, s = blk & 7;
        stageW0(smc, 128, (tile & 3) * 128, OFF_EW1, 1024, 512 + s * 64);
    } else if (blk < 128) {
        int i = blk - 64; int tile = i >> 3, s = i & 7;
        stageW0(smc, 128, (tile & 3) * 128, OFF_PRW, H, s * 64);
    }
    gwt(&gen);

    for (int t = 0; t < T_STEPS; t++) {
        const float* e1pre_t = g_e1pre + (size_t)t * BH;
        float (*d1)[BH] = g_d1P[t & 1];
        const float (*d1prev)[BH] = g_d1P[(t + 1) & 1];

        if (blk < 128) {
            // ======== chain blocks ========
            // ---- P1: e1h split8 (0-63), pr split8 (64-127)  [all NC=1]
            if (blk < 64) {
                int tile = blk >> 3, s = blk & 7;
                gemmT<2>(smc, (tile >> 2) * 128, (tile & 3) * 128, PLAIN(g_h),
                         H, s * 64, 64, OFF_EW1, 1024, 512 + s * 64,
                         0, 0, g_e1hP[s], H, 0, 1);
            } else {
                int i = blk - 64; int tile = i >> 3, s = i & 7;
                gemmT<2>(smc, (tile >> 2) * 128, (tile & 3) * 128, PLAIN(g_h),
                         H, s * 64, 64, OFF_PRW, H, s * 64,
                         s == 0 ? p.prb : 0, 0, g_prP[s], H, 0, 1);
            }
            garr(gen, 128, false);
            if (blk < 64) {                       // prefetch P2: ew2
                int tile = blk >> 3, s = blk & 7;
                stageW0(smc, 128, (tile & 3) * 128, OFF_EW2, H, s * 64);
            } else if (blk < 80) {                // pm
                int s = (blk - 64) & 7;
                stageW0(smc, 64, 0, OFF_PMW, H, s * 64);
            } else if (blk < 96) {                // ps
                int s = (blk - 80) & 7;
                stageW0(smc, 64, 0, OFF_PSW, H, s * 64);
            } else {                              // dw2 (d2prev)
                int i = blk - 96; int tile = i >> 2, s = i & 3;
                stageW0(smc, 128, (tile & 3) * 128, OFF_DW2, H, s * 128);
            }
            gwt(&gen);
            // ---- P2: e2 split8 (0-63), pm/ps split8 (64-95), d2prev split4 (96-127)
            if (blk < 64) {
                int tile = blk >> 3, s = blk & 7;
                ASrc a = {e1pre_t, g_e1hP[0], 0, 8, BH, 1};
                gemmT<2>(smc, (tile >> 2) * 128, (tile & 3) * 128, a,
                         H, s * 64, 64, OFF_EW2, H, s * 64,
                         s == 0 ? p.eb2 : 0, 0, g_e2P[s], H, 0, 1);
            } else if (blk < 96) {
                int i = blk - 64;
                int isps = i >> 4;
                int j = i & 15; int tile = j >> 3, s = j & 7;
                ASrc a = {0, g_prP[0], 0, 8, BH, 1};
                gemmT<1>(smc, tile * 128, 0, a, H, s * 64, 64,
                         isps ? OFF_PSW : OFF_PMW, H, s * 64,
                         s == 0 ? (isps ? p.psb : p.pmb) : 0, 0,
                         isps ? g_psP[s] : g_pmP[s], ZD, 0, 1);
            } else if (t > 0) {
                int i = blk - 96; int tile = i >> 2, s = i & 3;
                ASrc a = {0, d1prev[0], 0, 4, BH, 1};
                gemmT<2>(smc, (tile >> 2) * 128, (tile & 3) * 128, a,
                         H, s * 128, 128, OFF_DW2, H, s * 128,
                         s == 0 ? p.db2 : 0, 0, g_d2P[(t + 1) & 1][s], H, 0, 1);
            }
            garr(gen, 128, false);
            if (blk < 16) {                        // prefetch P3: emw
                int s = blk & 7;
                stageW0(smc, 64, 0, OFF_EMW, H, s * 64);
            } else if (blk < 32) {                 // esw
                int s = blk & 7;
                stageW0(smc, 64, 0, OFF_ESW, H, s * 64);
            } else if (blk < 64) {                 // dw1 (h half)
                int i = blk - 32; int tile = i >> 2, s = i & 3;
                stageW0(smc, 128, (tile & 3) * 128, OFF_DW1, 1024, 512 + s * 128);
            }
            gwt(&gen);
            // ---- P3: em split8 (0-15), es split8 (16-31), d1h split4 (32-63)
            if (blk < 32) {
                int ises = blk >> 4;
                int j = blk & 15; int tile = j >> 3, s = j & 7;
                ASrc a = {0, g_e2P[0], 0, 8, BH, 1};
                gemmT<1>(smc, tile * 128, 0, a, H, s * 64, 64,
                         ises ? OFF_ESW : OFF_EMW, H, s * 64,
                         s == 0 ? (ises ? p.esb : p.emb) : 0, 0,
                         ises ? g_esP[s] : g_emP[s], ZD, 0, 1);
            } else if (blk < 64) {
                int i = blk - 32; int tile = i >> 2, s = i & 3;
                gemmT<2>(smc, (tile >> 2) * 128, (tile & 3) * 128, PLAIN(g_h),
                         H, s * 128, 128, OFF_DW1, 1024, 512 + s * 128,
                         s == 0 ? p.db1 : 0, 0, d1[s], H, 0, 1);
            }
            garr(gen, 128, false);
            if (blk < 8) {                         // prefetch P4: pzw
                stageW0(smc, 128, (blk & 3) * 128, OFF_PZW, ZD, 0);
            }
            gwt(&gen);
            // ---- P4: pz (0-7, K=64), writers (8-39)
            {
                const float* eps_t = p.eps + (size_t)t * BZ;
                if (blk < 8) {
                    ASrc a = {eps_t, g_esP[0], g_emP[0], 8, BZ, 2};
                    gemmT<2>(smc, (blk >> 2) * 128, (blk & 3) * 128, a, ZD, 0, 64,
                             OFF_PZW, ZD, 0, p.pzb, 0, g_pz, H, 1, 1);
                } else if (blk < 40) {
                    float* z_t  = p.oz  + (size_t)t * BZ;
                    float* em_t = p.oem + (size_t)t * BZ;
                    float* es_t = p.oes + (size_t)t * BZ;
                    float* pm_t = p.opm + (size_t)t * BZ;
                    float* ps_t = p.ops + (size_t)t * BZ;
                    float* kl_t = p.okld + (size_t)t * BZ;
                    int base = (blk - 8) * 512;
                    for (int e = base + tid; e < base + 512; e += NTHR) {
                        float em = 0.f, es = 0.f, pm = 0.f, ps = 0.f;
#pragma unroll
                        for (int s = 0; s < 8; s++) {
                            em += g_emP[s][e]; es += g_esP[s][e];
                            pm += g_pmP[s][e]; ps += g_psP[s][e];
                        }
                        es = spf(es); ps = spf(ps);
                        em_t[e] = em; es_t[e] = es; pm_t[e] = pm; ps_t[e] = ps;
                        z_t[e] = eps_t[e] * es + em;
                        float d = em - pm;
                        kl_t[e] = 0.5f * (2.f * logf(ps) - 2.f * logf(es)
                                          + (es * es + d * d) / (ps * ps) - 1.f);
                    }
                }
            }
            garr(gen, 128, false);
            if (blk < 96) {                        // prefetch P5: gwih
                int tile = blk >> 2, s = blk & 3;
                stageW0(smc, 128, (tile % 12) * 128, OFF_GWIH, 1024, 512 + s * 128);
            } else {                               // dw1 (pz half)
                int i = blk - 96; int tile = i >> 2, s = i & 3;
                stageW0(smc, 128, (tile & 3) * 128, OFF_DW1, 1024, s * 128);
            }
            gwt(&gen);
            // ---- P5: gx_pz split4 (0-95), d1pz-fold split4 (96-127)
            if (blk < 96) {
                int tile = blk >> 2, s = blk & 3;
                gemmT<2>(smc, (tile / 12) * 128, (tile % 12) * 128, PLAIN(g_pz),
                         H, s * 128, 128, OFF_GWIH, 1024, 512 + s * 128,
                         0, 0, g_gxP[s], G3, 0, 1);
            } else {
                int i = blk - 96; int tile = i >> 2, s = i & 3;
                gemmT<2>(smc, (tile >> 2) * 128, (tile & 3) * 128, PLAIN(g_pz),
                         H, s * 128, 128, OFF_DW1, 1024, s * 128,
                         0, d1[s], d1[s], H, 0, 1);
            }
            garr(gen, 144, false);
            // prefetch next-step P1 W during bar5 (P6 GRU doesn't use smem W)
            if (blk < 64) {
                int tile = blk >> 3, s = blk & 7;
                stageW0(smc, 128, (tile & 3) * 128, OFF_EW1, 1024, 512 + s * 64);
            } else {
                int i = blk - 64; int tile = i >> 3, s = i & 7;
                stageW0(smc, 128, (tile & 3) * 128, OFF_PRW, H, s * 64);
            }
            gwt(&gen);
            // ---- P6: GRU on all 128 chain blocks (1024 elems each)
            {
                const float* gp = g_gxpre + (size_t)t * BG;
                int base = blk * 1024;
                for (int e = base + tid; e < base + 1024; e += NTHR) {
                    int b = e >> 9, j2 = e & 511;
                    size_t o = (size_t)b * G3 + j2;
                    float xr = gp[o], xz = gp[o + 512], xn = gp[o + 1024];
#pragma unroll
                    for (int s = 0; s < 4; s++) {
                        xr += g_gxP[s][o]; xz += g_gxP[s][o + 512]; xn += g_gxP[s][o + 1024];
                    }
                    float hr = g_gh[o], hz = g_gh[o + 512], hn = g_gh[o + 1024];
                    float rg = 1.f / (1.f + expf(-(xr + hr)));
                    float ug = 1.f / (1.f + expf(-(xz + hz)));
                    float ng = tanhf(xn + rg * hn);
                    g_h[e] = (1.f - ug) * ng + ug * g_h[e];
                }
            }
            gsyncN(&gen, 148, false);
        } else if (blk < 144) {
            // ======== background gh (h @ gwhh + gbhh, unsplit) ========
            int b = blk - 128;
            {
                int tile = b;
                gemmT<2>(smc, (tile / 12) * 128, (tile % 12) * 128, PLAIN(g_h),
                         H, 0, 512, OFF_GWHH, H, 0, p.gbhh, 0, g_gh, G3, 0, 0);
            }
            if (b < 8) {
                int tile2 = 16 + b;
                gemmT<2>(smc, (tile2 / 12) * 128, (tile2 % 12) * 128, PLAIN(g_h),
                         H, 0, 512, OFF_GWHH, H, 0, p.gbhh, 0, g_gh, G3, 0, 0);
            }
            if (tid == 0) { while (g_sense < gen + 4) __nanosleep(32); }
            gen += 4;
            gsyncN(&gen, 144, false);   // bar5
            gsyncN(&gen, 148, false);   // bar6
        } else {
            // ======== background logits(t-1): d2(t-1) lands at P2 ========
            int b = blk - 144;
            if (tid == 0) { while (g_sense < gen + 2) __nanosleep(32); }
            __syncthreads();
            if (t > 0) {
                ASrc a = {0, g_d2P[(t + 1) & 1][0], 0, 4, BH, 1};
                gemmT<2>(smc, (b >> 1) * 128, (b & 1) * 128, a, H, 0, 512,
                         OFF_DLW, H, 0, p.dlb, 0,
                         p.olog + (size_t)(t - 1) * BO, OD, 0, 0);
            }
            if (tid == 0) { while (g_sense < gen + 5) __nanosleep(32); }
            gen += 5;
            gsyncN(&gen, 148, false);   // bar6
        }
    }
    // ---- tail: d2(199) then logits(199) ----
    if (blk < 32) {
        int tile = blk >> 2, s = blk & 3;
        ASrc a = {0, g_d1P[(T_STEPS - 1) & 1][0], 0, 4, BH, 1};
        gemmT<2>(smc, (tile >> 2) * 128, (tile & 3) * 128, a, H, s * 128, 128,
                 OFF_DW2, H, s * 128, s == 0 ? p.db2 : 0, 0,
                 g_d2P[(T_STEPS - 1) & 1][s], H, 0, 0);
    }
    gsyncN(&gen, NBLK, false);
    if (blk < 4) {
        ASrc a = {0, g_d2P[(T_STEPS - 1) & 1][0], 0, 4, BH, 1};
        gemmT<2>(smc, (blk >> 1) * 128, (blk & 1) * 128, a, H, 0, 512,
                 OFF_DLW, H, 0, p.dlb, 0,
                 p.olog + (size_t)(T_STEPS - 1) * BO, OD, 0, 0);
    }
    gsyncN(&gen, NBLK, true);
}

extern "C" void kernel_launch(void* const* d_in, const int* in_sizes, int n_in,
                              void* d_out, int out_size) {
    Params p;
    p.x    = (const float*)d_in[0];
    p.eps  = (const float*)d_in[1];
    p.pxw1 = (const float*)d_in[2];  p.pxb1 = (const float*)d_in[3];
    p.pxw2 = (const float*)d_in[4];  p.pxb2 = (const float*)d_in[5];
    p.pzw  = (const float*)d_in[6];  p.pzb  = (const float*)d_in[7];
    p.ew1  = (const float*)d_in[8];  p.eb1  = (const float*)d_in[9];
    p.ew2  = (const float*)d_in[10]; p.eb2  = (const float*)d_in[11];
    p.emw  = (const float*)d_in[12]; p.emb  = (const float*)d_in[13];
    p.esw  = (const float*)d_in[14]; p.esb  = (const float*)d_in[15];
    p.prw  = (const float*)d_in[16]; p.prb  = (const float*)d_in[17];
    p.pmw  = (const float*)d_in[18]; p.pmb  = (const float*)d_in[19];
    p.psw  = (const float*)d_in[20]; p.psb  = (const float*)d_in[21];
    p.dw1  = (const float*)d_in[22]; p.db1  = (const float*)d_in[23];
    p.dw2  = (const float*)d_in[24]; p.db2  = (const float*)d_in[25];
    p.dlw  = (const float*)d_in[26]; p.dlb  = (const float*)d_in[27];
    if (in_sizes[29] == 3 * H) {
        p.gwih = (const float*)d_in[28]; p.gbih = (const float*)d_in[29];
        p.gwhh = (const float*)d_in[30]; p.gbhh = (const float*)d_in[31];
    } else {
        p.gwih = (const float*)d_in[28]; p.gwhh = (const float*)d_in[29];
        p.gbih = (const float*)d_in[30]; p.gbhh = (const float*)d_in[31];
    }

    float* o = (float*)d_out;
    size_t TBZ = (size_t)T_STEPS * B * ZD;
    size_t TBO = (size_t)T_STEPS * B * OD;
    p.oz   = o;
    p.olog = o + TBZ;
    p.oem  = p.olog + TBO;
    p.oes  = p.oem + TBZ;
    p.opm  = p.oes + TBZ;
    p.ops  = p.opm + TBZ;
    p.okld = p.ops + TBZ;

    static bool attr_set = false;
    if (!attr_set) {
        cudaFuncSetAttribute(vrnn_kernel, cudaFuncAttributeMaxDynamicSharedMemorySize, SMEM_BYTES);
        attr_set = true;
    }
    vrnn_kernel<<<NBLK, NTHR, SMEM_BYTES>>>(p);
}